// round 1
// baseline (speedup 1.0000x reference)
#include <cuda_runtime.h>
#include <math.h>

#define NF 32
#define WPB 8                    // warps (== samples) per block
#define THREADS (WPB * 32)
#define WP_FLOATS 8192           // one packed weight array (32x256 floats)
#define SAMP_STRIDE 3392         // per-sample smem scratch in floats

// Per-sample scratch layout (floats, relative to S):
//   [0..63]      a(16) @0, b(16) @16, c(16) @32, pad
//   [64..1087]   act1[4][256]   conv0 output for 4 d1-positions (im2col rows for conv1)
//   [1088..3135] act2[8][256]   relu(y1) im2col for conv2
//   [3136..3391] act3[256]      relu(y2) im2col for conv3

__global__ __launch_bounds__(THREADS, 1)
void NTC_30202210025785_kernel(
    const int*   __restrict__ gi, const int* __restrict__ gj, const int* __restrict__ gk,
    const float* __restrict__ A,  const float* __restrict__ Bm, const float* __restrict__ Cm,
    const float* __restrict__ W0, const float* __restrict__ b0,
    const float* __restrict__ W1, const float* __restrict__ b1,
    const float* __restrict__ W2, const float* __restrict__ b2,
    const float* __restrict__ W3, const float* __restrict__ b3,
    const float* __restrict__ fcw, const float* __restrict__ fcb,
    float* __restrict__ out)
{
    extern __shared__ float smem[];
    float* Wp1 = smem;                     // packed [kb][g] float4 views
    float* Wp2 = Wp1 + WP_FLOATS;
    float* Wp3 = Wp2 + WP_FLOATS;
    float* sampBase = Wp3 + WP_FLOATS;

    const int tid = threadIdx.x;

    // ---- pack W1/W2/W3 into smem as [kb (64)][g (32)] float4 (conflict-free reads) ----
    {
        const float4* w1v = (const float4*)W1;
        const float4* w2v = (const float4*)W2;
        const float4* w3v = (const float4*)W3;
        float4* p1 = (float4*)Wp1;
        float4* p2 = (float4*)Wp2;
        float4* p3 = (float4*)Wp3;
        for (int e = tid; e < 2048; e += THREADS) {
            int g = e >> 6, kb = e & 63;
            int dst = kb * 32 + g;
            p1[dst] = w1v[e];
            p2[dst] = w2v[e];
            p3[dst] = w3v[e];
        }
    }
    __syncthreads();

    const int warp = tid >> 5;
    const int lane = tid & 31;
    const int sample = blockIdx.x * WPB + warp;

    float* S    = sampBase + warp * SAMP_STRIDE;
    float* sa   = S;
    float* sb   = S + 16;
    float* sc   = S + 32;
    float* act1 = S + 64;
    float* act2 = S + 64 + 1024;
    float* act3 = S + 64 + 1024 + 2048;

    // ---- load per-sample factor rows ----
    {
        const int ii = gi[sample];
        const int jj = gj[sample];
        const int kk = gk[sample];
        if (lane < 16) {
            sa[lane] = A [ii * 16 + lane];
            sb[lane] = Bm[jj * 16 + lane];
            sc[lane] = Cm[kk * 16 + lane];
        }
    }
    __syncwarp();

    const int g = lane;  // this lane's channel (f for conv0 producer, g for consumers)

    // per-lane conv0 kernel (8 taps) and biases
    float w0r[8];
#pragma unroll
    for (int q = 0; q < 8; q++) w0r[q] = W0[g * 8 + q];
    const float bias0 = b0[g];
    const float bias1 = b1[g];
    const float bias2 = b2[g];
    const float bias3 = b3[g];

    const float4* wv1 = ((const float4*)Wp1) + g;
    const float4* wv2 = ((const float4*)Wp2) + g;
    const float4* wv3 = ((const float4*)Wp3) + g;

    // ================= conv0 + conv1, grouped 4 d1-positions per weight pass =========
    for (int h1 = 0; h1 < 4; h1++) {
        for (int w1 = 0; w1 < 4; w1++) {
            // b/c segments for this (h1,w1)
            float bb4[4], cc4[4];
#pragma unroll
            for (int q = 0; q < 4; q++) { bb4[q] = sb[4 * h1 + q]; cc4[q] = sc[4 * w1 + q]; }
            float bcp[16];
#pragma unroll
            for (int i0 = 0; i0 < 4; i0++)
#pragma unroll
                for (int j0 = 0; j0 < 4; j0++)
                    bcp[i0 * 4 + j0] = bb4[i0] * cc4[j0];

            // u[dd][hh0*2+ww0]: depends only on (h1,w1), shared across all 4 d1
            float u[2][4];
#pragma unroll
            for (int dd = 0; dd < 2; dd++)
#pragma unroll
                for (int hh0 = 0; hh0 < 2; hh0++)
#pragma unroll
                    for (int ww0 = 0; ww0 < 2; ww0++) {
                        float v;
                        v = w0r[dd * 4 + 0] * bcp[(2 * hh0)     * 4 + 2 * ww0    ];
                        v = fmaf(w0r[dd * 4 + 1], bcp[(2 * hh0)     * 4 + 2 * ww0 + 1], v);
                        v = fmaf(w0r[dd * 4 + 2], bcp[(2 * hh0 + 1) * 4 + 2 * ww0    ], v);
                        v = fmaf(w0r[dd * 4 + 3], bcp[(2 * hh0 + 1) * 4 + 2 * ww0 + 1], v);
                        u[dd][hh0 * 2 + ww0] = v;
                    }

            // y0 blocks for 4 d1 positions -> relu -> act1[d1][f*8 + corner]
#pragma unroll
            for (int d1 = 0; d1 < 4; d1++) {
                float a0 = sa[4 * d1 + 0], a1 = sa[4 * d1 + 1];
                float a2 = sa[4 * d1 + 2], a3 = sa[4 * d1 + 3];
                float y[8];
#pragma unroll
                for (int q = 0; q < 4; q++) {
                    y[q]     = fmaxf(fmaf(u[1][q], a1, fmaf(u[0][q], a0, bias0)), 0.f);
                    y[4 + q] = fmaxf(fmaf(u[1][q], a3, fmaf(u[0][q], a2, bias0)), 0.f);
                }
                float4* dst = (float4*)(act1 + d1 * 256 + g * 8);
                dst[0] = make_float4(y[0], y[1], y[2], y[3]);
                dst[1] = make_float4(y[4], y[5], y[6], y[7]);
            }
            __syncwarp();

            // conv1: 4 outputs (one per d1) per lane, one pass over W1 row
            float s0 = bias1, s1 = bias1, s2 = bias1, s3 = bias1;
            const float4* a0v = (const float4*)(act1);
            const float4* a1v = (const float4*)(act1 + 256);
            const float4* a2v = (const float4*)(act1 + 512);
            const float4* a3v = (const float4*)(act1 + 768);
#pragma unroll 4
            for (int kb = 0; kb < 64; kb++) {
                float4 w  = wv1[kb * 32];
                float4 x0 = a0v[kb];
                float4 x1 = a1v[kb];
                float4 x2 = a2v[kb];
                float4 x3 = a3v[kb];
                s0 = fmaf(w.x, x0.x, s0); s0 = fmaf(w.y, x0.y, s0);
                s0 = fmaf(w.z, x0.z, s0); s0 = fmaf(w.w, x0.w, s0);
                s1 = fmaf(w.x, x1.x, s1); s1 = fmaf(w.y, x1.y, s1);
                s1 = fmaf(w.z, x1.z, s1); s1 = fmaf(w.w, x1.w, s1);
                s2 = fmaf(w.x, x2.x, s2); s2 = fmaf(w.y, x2.y, s2);
                s2 = fmaf(w.z, x2.z, s2); s2 = fmaf(w.w, x2.w, s2);
                s3 = fmaf(w.x, x3.x, s3); s3 = fmaf(w.y, x3.y, s3);
                s3 = fmaf(w.z, x3.z, s3); s3 = fmaf(w.w, x3.w, s3);
            }

            // relu(y1) scatter into conv2 im2col act2[p2][g*8 + c2]
            {
                const int h2 = h1 >> 1, hh2 = h1 & 1;
                const int w2 = w1 >> 1, ww2 = w1 & 1;
                float sv[4] = {s0, s1, s2, s3};
#pragma unroll
                for (int d1 = 0; d1 < 4; d1++) {
                    int d2 = d1 >> 1, dd2 = d1 & 1;
                    int p2 = d2 * 4 + h2 * 2 + w2;
                    int c2 = dd2 * 4 + hh2 * 2 + ww2;
                    act2[p2 * 256 + g * 8 + c2] = fmaxf(sv[d1], 0.f);
                }
            }
            __syncwarp();
        }
    }

    // ================= conv2 =================
#pragma unroll
    for (int p2 = 0; p2 < 8; p2++) {
        const float4* av = (const float4*)(act2 + p2 * 256);
        float q0 = bias2, q1 = 0.f, q2 = 0.f, q3 = 0.f;
#pragma unroll 4
        for (int kb = 0; kb < 64; kb += 4) {
            float4 w0v = wv2[(kb + 0) * 32]; float4 x0 = av[kb + 0];
            float4 w1v = wv2[(kb + 1) * 32]; float4 x1 = av[kb + 1];
            float4 w2v = wv2[(kb + 2) * 32]; float4 x2 = av[kb + 2];
            float4 w3v = wv2[(kb + 3) * 32]; float4 x3 = av[kb + 3];
            q0 = fmaf(w0v.x, x0.x, q0); q0 = fmaf(w0v.y, x0.y, q0);
            q0 = fmaf(w0v.z, x0.z, q0); q0 = fmaf(w0v.w, x0.w, q0);
            q1 = fmaf(w1v.x, x1.x, q1); q1 = fmaf(w1v.y, x1.y, q1);
            q1 = fmaf(w1v.z, x1.z, q1); q1 = fmaf(w1v.w, x1.w, q1);
            q2 = fmaf(w2v.x, x2.x, q2); q2 = fmaf(w2v.y, x2.y, q2);
            q2 = fmaf(w2v.z, x2.z, q2); q2 = fmaf(w2v.w, x2.w, q2);
            q3 = fmaf(w3v.x, x3.x, q3); q3 = fmaf(w3v.y, x3.y, q3);
            q3 = fmaf(w3v.z, x3.z, q3); q3 = fmaf(w3v.w, x3.w, q3);
        }
        act3[g * 8 + p2] = fmaxf((q0 + q1) + (q2 + q3), 0.f);
    }
    __syncwarp();

    // ================= conv3 + fc + sigmoid =================
    {
        const float4* av = (const float4*)(act3);
        float q0 = bias3, q1 = 0.f, q2 = 0.f, q3 = 0.f;
#pragma unroll 4
        for (int kb = 0; kb < 64; kb += 4) {
            float4 w0v = wv3[(kb + 0) * 32]; float4 x0 = av[kb + 0];
            float4 w1v = wv3[(kb + 1) * 32]; float4 x1 = av[kb + 1];
            float4 w2v = wv3[(kb + 2) * 32]; float4 x2 = av[kb + 2];
            float4 w3v = wv3[(kb + 3) * 32]; float4 x3 = av[kb + 3];
            q0 = fmaf(w0v.x, x0.x, q0); q0 = fmaf(w0v.y, x0.y, q0);
            q0 = fmaf(w0v.z, x0.z, q0); q0 = fmaf(w0v.w, x0.w, q0);
            q1 = fmaf(w1v.x, x1.x, q1); q1 = fmaf(w1v.y, x1.y, q1);
            q1 = fmaf(w1v.z, x1.z, q1); q1 = fmaf(w1v.w, x1.w, q1);
            q2 = fmaf(w2v.x, x2.x, q2); q2 = fmaf(w2v.y, x2.y, q2);
            q2 = fmaf(w2v.z, x2.z, q2); q2 = fmaf(w2v.w, x2.w, q2);
            q3 = fmaf(w3v.x, x3.x, q3); q3 = fmaf(w3v.y, x3.y, q3);
            q3 = fmaf(w3v.z, x3.z, q3); q3 = fmaf(w3v.w, x3.w, q3);
        }
        float y3 = fmaxf((q0 + q1) + (q2 + q3), 0.f);
        float v = y3 * fcw[g];
#pragma unroll
        for (int off = 16; off > 0; off >>= 1)
            v += __shfl_xor_sync(0xffffffffu, v, off);
        if (lane == 0) {
            float z = v + fcb[0];
            out[sample] = 1.0f / (1.0f + expf(-z));
        }
    }
}

extern "C" void kernel_launch(void* const* d_in, const int* in_sizes, int n_in,
                              void* d_out, int out_size)
{
    const int*   gi  = (const int*)  d_in[0];
    const int*   gj  = (const int*)  d_in[1];
    const int*   gk  = (const int*)  d_in[2];
    const float* A   = (const float*)d_in[3];
    const float* Bm  = (const float*)d_in[4];
    const float* Cm  = (const float*)d_in[5];
    const float* W0  = (const float*)d_in[6];
    const float* b0  = (const float*)d_in[7];
    const float* W1  = (const float*)d_in[8];
    const float* b1  = (const float*)d_in[9];
    const float* W2  = (const float*)d_in[10];
    const float* b2  = (const float*)d_in[11];
    const float* W3  = (const float*)d_in[12];
    const float* b3  = (const float*)d_in[13];
    const float* fcw = (const float*)d_in[14];
    const float* fcb = (const float*)d_in[15];
    float* out = (float*)d_out;

    const int batch  = in_sizes[0];
    const int blocks = batch / WPB;
    const size_t smemBytes = (size_t)(3 * WP_FLOATS + WPB * SAMP_STRIDE) * sizeof(float);

    cudaFuncSetAttribute(NTC_30202210025785_kernel,
                         cudaFuncAttributeMaxDynamicSharedMemorySize, (int)smemBytes);

    NTC_30202210025785_kernel<<<blocks, THREADS, smemBytes>>>(
        gi, gj, gk, A, Bm, Cm, W0, b0, W1, b1, W2, b2, W3, b3, fcw, fcb, out);
}

// round 2
// speedup vs baseline: 1.3384x; 1.3384x over previous
#include <cuda_runtime.h>
#include <math.h>

#define WPB 8
#define THREADS 256
#define WPFL 8192                 // one packed weight buffer (floats)
#define SSTR 4416                 // per-sample scratch floats: 64 bc | 2048 act1 | 2048 act2 | 256 act3

__device__ __forceinline__ void ffma2(unsigned long long& d,
                                      unsigned long long a,
                                      unsigned long long b) {
    asm("fma.rn.f32x2 %0, %1, %2, %0;" : "+l"(d) : "l"(a), "l"(b));
}
__device__ __forceinline__ float2 upk2(unsigned long long v) {
    float lo, hi;
    asm("mov.b64 {%0, %1}, %2;" : "=f"(lo), "=f"(hi) : "l"(v));
    return make_float2(lo, hi);
}

__global__ __launch_bounds__(THREADS, 1)
void NTC_30202210025785_kernel(
    const int*   __restrict__ gi, const int* __restrict__ gj, const int* __restrict__ gk,
    const float* __restrict__ A,  const float* __restrict__ Bm, const float* __restrict__ Cm,
    const float* __restrict__ W0, const float* __restrict__ b0,
    const float* __restrict__ W1, const float* __restrict__ b1,
    const float* __restrict__ W2, const float* __restrict__ b2,
    const float* __restrict__ W3, const float* __restrict__ b3,
    const float* __restrict__ fcw, const float* __restrict__ fcb,
    float* __restrict__ out)
{
    extern __shared__ float smem[];
    float* Wp1 = smem;            // holds packed W1; later repacked with W3
    float* Wp2 = smem + WPFL;     // packed W2
    float* sampBase = smem + 2 * WPFL;

    const int tid = threadIdx.x;

    // ---- pack W1 / W2 into smem: float4 index (half*32 + c)*32 + g,
    //      where float4 = W[g][c][half*4 .. half*4+3] (contiguous in gmem) ----
    {
        const float4* w1v = (const float4*)W1;
        const float4* w2v = (const float4*)W2;
        float4* p1 = (float4*)Wp1;
        float4* p2 = (float4*)Wp2;
        for (int e = tid; e < 2048; e += THREADS) {
            int gg = e >> 6, rem = e & 63, cc_ = rem >> 1, hf = rem & 1;
            int dst = (hf * 32 + cc_) * 32 + gg;
            p1[dst] = w1v[e];
            p2[dst] = w2v[e];
        }
    }
    __syncthreads();

    const int warp = tid >> 5;
    const int lane = tid & 31;
    const int g = lane;
    const int sample = blockIdx.x * WPB + warp;

    float* sbc  = sampBase + warp * SSTR;      // b[16], c[16]
    float* act1 = sbc + 64;                    // 8 rows x 256 (k = dd*128 + c*4 + hh*2+ww)
    float* act2 = act1 + 2048;                 // 8 rows x 256 (k = dd2*128 + g*4 + hh2*2+ww2)
    float* act3 = act2 + 2048;                 // 256        (k = (p2>>2)*128 + g*4 + (p2&3))
    ulonglong2* act1u = (ulonglong2*)act1;
    ulonglong2* act2u = (ulonglong2*)act2;
    ulonglong2* act3u = (ulonglong2*)act3;

    // ---- per-sample factors: a in registers, b/c in smem ----
    float ar[16];
    {
        const int ii = gi[sample];
        const int jj = gj[sample];
        const int kk = gk[sample];
        const float4* Av = (const float4*)(A + ii * 16);
#pragma unroll
        for (int q = 0; q < 4; q++) {
            float4 v = Av[q];
            ar[4 * q + 0] = v.x; ar[4 * q + 1] = v.y; ar[4 * q + 2] = v.z; ar[4 * q + 3] = v.w;
        }
        if (lane < 16) {
            sbc[lane]      = Bm[jj * 16 + lane];
            sbc[16 + lane] = Cm[kk * 16 + lane];
        }
    }
    __syncwarp();

    // per-lane conv0 taps + biases
    float w0r[8];
    {
        const float4* w0v = (const float4*)W0;
        float4 wa = w0v[g * 2], wb = w0v[g * 2 + 1];
        w0r[0] = wa.x; w0r[1] = wa.y; w0r[2] = wa.z; w0r[3] = wa.w;
        w0r[4] = wb.x; w0r[5] = wb.y; w0r[6] = wb.z; w0r[7] = wb.w;
    }
    const float bias0 = b0[g];
    const float bias1 = b1[g];
    const float bias2 = b2[g];
    const float bias3 = b3[g];
    const float fcwg  = fcw[g];

    const ulonglong2* wv1 = ((const ulonglong2*)Wp1) + g;
    const ulonglong2* wv2 = ((const ulonglong2*)Wp2) + g;

    // ================= conv0 + conv1: 8 passes, 8 outputs per weight pass =========
    for (int pass = 0; pass < 8; pass++) {
        const int h1  = pass >> 1;
        const int w1p = pass & 1;

        // --- conv0: build 8 im2col rows (r = w1s*4 + d1) ---
#pragma unroll
        for (int w1s = 0; w1s < 2; w1s++) {
            const int w1 = w1p * 2 + w1s;
            float bb[4], cc[4];
#pragma unroll
            for (int q = 0; q < 4; q++) { bb[q] = sbc[4 * h1 + q]; cc[q] = sbc[16 + 4 * w1 + q]; }
            float bcp[16];
#pragma unroll
            for (int i0 = 0; i0 < 4; i0++)
#pragma unroll
                for (int j0 = 0; j0 < 4; j0++)
                    bcp[i0 * 4 + j0] = bb[i0] * cc[j0];

            float u0[4], u1[4];
#pragma unroll
            for (int hh = 0; hh < 2; hh++)
#pragma unroll
                for (int ww = 0; ww < 2; ww++) {
                    const int q = hh * 2 + ww;
                    float v0, v1;
                    v0 =      w0r[0] * bcp[(2 * hh) * 4 + 2 * ww];
                    v0 = fmaf(w0r[1],  bcp[(2 * hh) * 4 + 2 * ww + 1], v0);
                    v0 = fmaf(w0r[2],  bcp[(2 * hh + 1) * 4 + 2 * ww], v0);
                    v0 = fmaf(w0r[3],  bcp[(2 * hh + 1) * 4 + 2 * ww + 1], v0);
                    v1 =      w0r[4] * bcp[(2 * hh) * 4 + 2 * ww];
                    v1 = fmaf(w0r[5],  bcp[(2 * hh) * 4 + 2 * ww + 1], v1);
                    v1 = fmaf(w0r[6],  bcp[(2 * hh + 1) * 4 + 2 * ww], v1);
                    v1 = fmaf(w0r[7],  bcp[(2 * hh + 1) * 4 + 2 * ww + 1], v1);
                    u0[q] = v0; u1[q] = v1;
                }

#pragma unroll
            for (int d1 = 0; d1 < 4; d1++) {
                const float a0 = ar[4 * d1 + 0], a1 = ar[4 * d1 + 1];
                const float a2 = ar[4 * d1 + 2], a3 = ar[4 * d1 + 3];
                float y[8];
#pragma unroll
                for (int q = 0; q < 4; q++) {
                    y[q]     = fmaxf(fmaf(u1[q], a1, fmaf(u0[q], a0, bias0)), 0.f);
                    y[4 + q] = fmaxf(fmaf(u1[q], a3, fmaf(u0[q], a2, bias0)), 0.f);
                }
                const int r = w1s * 4 + d1;
                ((float4*)act1)[r * 64 + g]      = make_float4(y[0], y[1], y[2], y[3]); // dd=0
                ((float4*)act1)[r * 64 + 32 + g] = make_float4(y[4], y[5], y[6], y[7]); // dd=1
            }
        }
        __syncwarp();

        // --- conv1: 8 outputs per lane in one pass over W1 (packed f32x2) ---
        unsigned long long acc[8];
#pragma unroll
        for (int r = 0; r < 8; r++) acc[r] = 0ull;
#pragma unroll 4
        for (int kb = 0; kb < 64; kb++) {
            const ulonglong2 w = wv1[kb * 32];
#pragma unroll
            for (int r = 0; r < 8; r++) {
                const ulonglong2 x = act1u[r * 64 + kb];
                ffma2(acc[r], w.x, x.x);
                ffma2(acc[r], w.y, x.y);
            }
        }

        // --- relu + scatter into conv2 im2col ---
        const int h2 = h1 >> 1, hh2 = h1 & 1;
#pragma unroll
        for (int r = 0; r < 8; r++) {
            const int w1s = r >> 2, d1 = r & 3;
            const int d2 = d1 >> 1, dd2 = d1 & 1;
            const float2 p = upk2(acc[r]);
            const float s = fmaxf(p.x + p.y + bias1, 0.f);
            const int p2 = d2 * 4 + h2 * 2 + w1p;          // w2 == w1p
            act2[p2 * 256 + dd2 * 128 + g * 4 + hh2 * 2 + w1s] = s;
        }
        __syncwarp();
    }

    // ---- repack Wp1 <- W3 (conv1 done block-wide) ----
    __syncthreads();
    {
        const float4* w3v = (const float4*)W3;
        float4* p1 = (float4*)Wp1;
        for (int e = tid; e < 2048; e += THREADS) {
            int gg = e >> 6, rem = e & 63, cc_ = rem >> 1, hf = rem & 1;
            p1[(hf * 32 + cc_) * 32 + gg] = w3v[e];
        }
    }
    __syncthreads();

    // ================= conv2: all 8 positions in one weight pass =================
    {
        unsigned long long q[8];
#pragma unroll
        for (int p2 = 0; p2 < 8; p2++) q[p2] = 0ull;
#pragma unroll 2
        for (int kb = 0; kb < 64; kb++) {
            const ulonglong2 w = wv2[kb * 32];
#pragma unroll
            for (int p2 = 0; p2 < 8; p2++) {
                const ulonglong2 x = act2u[p2 * 64 + kb];
                ffma2(q[p2], w.x, x.x);
                ffma2(q[p2], w.y, x.y);
            }
        }
        float y2[8];
#pragma unroll
        for (int p2 = 0; p2 < 8; p2++) {
            const float2 p = upk2(q[p2]);
            y2[p2] = fmaxf(p.x + p.y + bias2, 0.f);
        }
        ((float4*)act3)[g]      = make_float4(y2[0], y2[1], y2[2], y2[3]); // half=0
        ((float4*)act3)[32 + g] = make_float4(y2[4], y2[5], y2[6], y2[7]); // half=1
    }
    __syncwarp();

    // ================= conv3 + fc + sigmoid =================
    {
        const ulonglong2* wv3 = ((const ulonglong2*)Wp1) + g;
        unsigned long long e0 = 0ull, e1 = 0ull;
#pragma unroll 8
        for (int kb = 0; kb < 64; kb++) {
            const ulonglong2 w = wv3[kb * 32];
            const ulonglong2 x = act3u[kb];
            ffma2(e0, w.x, x.x);
            ffma2(e1, w.y, x.y);
        }
        const float2 pa = upk2(e0), pb = upk2(e1);
        const float y3 = fmaxf((pa.x + pa.y) + (pb.x + pb.y) + bias3, 0.f);
        float v = y3 * fcwg;
#pragma unroll
        for (int off = 16; off > 0; off >>= 1)
            v += __shfl_xor_sync(0xffffffffu, v, off);
        if (lane == 0) {
            const float z = v + fcb[0];
            out[sample] = 1.0f / (1.0f + expf(-z));
        }
    }
}

extern "C" void kernel_launch(void* const* d_in, const int* in_sizes, int n_in,
                              void* d_out, int out_size)
{
    const int*   gi  = (const int*)  d_in[0];
    const int*   gj  = (const int*)  d_in[1];
    const int*   gk  = (const int*)  d_in[2];
    const float* A   = (const float*)d_in[3];
    const float* Bm  = (const float*)d_in[4];
    const float* Cm  = (const float*)d_in[5];
    const float* W0  = (const float*)d_in[6];
    const float* b0  = (const float*)d_in[7];
    const float* W1  = (const float*)d_in[8];
    const float* b1  = (const float*)d_in[9];
    const float* W2  = (const float*)d_in[10];
    const float* b2  = (const float*)d_in[11];
    const float* W3  = (const float*)d_in[12];
    const float* b3  = (const float*)d_in[13];
    const float* fcw = (const float*)d_in[14];
    const float* fcb = (const float*)d_in[15];
    float* out = (float*)d_out;

    const int batch  = in_sizes[0];
    const int blocks = batch / WPB;
    const size_t smemBytes = (size_t)(2 * WPFL + WPB * SSTR) * sizeof(float);

    cudaFuncSetAttribute(NTC_30202210025785_kernel,
                         cudaFuncAttributeMaxDynamicSharedMemorySize, (int)smemBytes);

    NTC_30202210025785_kernel<<<blocks, THREADS, smemBytes>>>(
        gi, gj, gk, A, Bm, Cm, W0, b0, W1, b1, W2, b2, W3, b3, fcw, fcb, out);
}

// round 3
// speedup vs baseline: 1.3437x; 1.0039x over previous
#include <cuda_runtime.h>
#include <math.h>

#define WPB 8
#define THREADS 256
#define WPFL 8192                 // one packed weight buffer (floats)
#define SSTR 4416                 // per-sample scratch floats: 64 bc | 2048 act1 | 2048 act2 | 256 act3

__device__ __forceinline__ void ffma2(unsigned long long& d,
                                      unsigned long long a,
                                      unsigned long long b) {
    asm("fma.rn.f32x2 %0, %1, %2, %0;" : "+l"(d) : "l"(a), "l"(b));
}
__device__ __forceinline__ float2 upk2(unsigned long long v) {
    float lo, hi;
    asm("mov.b64 {%0, %1}, %2;" : "=f"(lo), "=f"(hi) : "l"(v));
    return make_float2(lo, hi);
}

__global__ __launch_bounds__(THREADS, 1)
void NTC_30202210025785_kernel(
    const int*   __restrict__ gi, const int* __restrict__ gj, const int* __restrict__ gk,
    const float* __restrict__ A,  const float* __restrict__ Bm, const float* __restrict__ Cm,
    const float* __restrict__ W0, const float* __restrict__ b0,
    const float* __restrict__ W1, const float* __restrict__ b1,
    const float* __restrict__ W2, const float* __restrict__ b2,
    const float* __restrict__ W3, const float* __restrict__ b3,
    const float* __restrict__ fcw, const float* __restrict__ fcb,
    float* __restrict__ out)
{
    extern __shared__ float smem[];
    float* Wp1 = smem;            // holds packed W1; later repacked with W3
    float* Wp2 = smem + WPFL;     // packed W2
    float* sampBase = smem + 2 * WPFL;

    const int tid = threadIdx.x;

    // ---- pack W1 / W2 into smem: float4 index (half*32 + c)*32 + g,
    //      where float4 = W[g][c][half*4 .. half*4+3] (contiguous in gmem) ----
    {
        const float4* w1v = (const float4*)W1;
        const float4* w2v = (const float4*)W2;
        float4* p1 = (float4*)Wp1;
        float4* p2 = (float4*)Wp2;
        for (int e = tid; e < 2048; e += THREADS) {
            int gg = e >> 6, rem = e & 63, cc_ = rem >> 1, hf = rem & 1;
            int dst = (hf * 32 + cc_) * 32 + gg;
            p1[dst] = w1v[e];
            p2[dst] = w2v[e];
        }
    }
    __syncthreads();

    const int warp = tid >> 5;
    const int lane = tid & 31;
    const int g = lane;
    const int sample = blockIdx.x * WPB + warp;

    float* sbc  = sampBase + warp * SSTR;      // b[16], c[16]
    float* act1 = sbc + 64;                    // 8 rows x 256 (k = dd*128 + c*4 + hh*2+ww)
    float* act2 = act1 + 2048;                 // 8 rows x 256 (k = dd2*128 + g*4 + hh2*2+ww2)
    float* act3 = act2 + 2048;                 // 256        (k = (p2>>2)*128 + g*4 + (p2&3))
    ulonglong2* act1u = (ulonglong2*)act1;
    ulonglong2* act2u = (ulonglong2*)act2;
    ulonglong2* act3u = (ulonglong2*)act3;

    // ---- per-sample factors: a in registers, b/c in smem ----
    float ar[16];
    {
        const int ii = gi[sample];
        const int jj = gj[sample];
        const int kk = gk[sample];
        const float4* Av = (const float4*)(A + ii * 16);
#pragma unroll
        for (int q = 0; q < 4; q++) {
            float4 v = Av[q];
            ar[4 * q + 0] = v.x; ar[4 * q + 1] = v.y; ar[4 * q + 2] = v.z; ar[4 * q + 3] = v.w;
        }
        if (lane < 16) {
            sbc[lane]      = Bm[jj * 16 + lane];
            sbc[16 + lane] = Cm[kk * 16 + lane];
        }
    }
    __syncwarp();

    // per-lane conv0 taps + biases
    float w0r[8];
    {
        const float4* w0v = (const float4*)W0;
        float4 wa = w0v[g * 2], wb = w0v[g * 2 + 1];
        w0r[0] = wa.x; w0r[1] = wa.y; w0r[2] = wa.z; w0r[3] = wa.w;
        w0r[4] = wb.x; w0r[5] = wb.y; w0r[6] = wb.z; w0r[7] = wb.w;
    }
    const float bias0 = b0[g];
    const float bias1 = b1[g];
    const float bias2 = b2[g];
    const float bias3 = b3[g];
    const float fcwg  = fcw[g];

    const ulonglong2* wv1 = ((const ulonglong2*)Wp1) + g;
    const ulonglong2* wv2 = ((const ulonglong2*)Wp2) + g;

    // ================= conv0 + conv1: 8 passes, 8 outputs per weight pass =========
    for (int pass = 0; pass < 8; pass++) {
        const int h1  = pass >> 1;
        const int w1p = pass & 1;

        // --- conv0: build 8 im2col rows (r = w1s*4 + d1) ---
#pragma unroll
        for (int w1s = 0; w1s < 2; w1s++) {
            const int w1 = w1p * 2 + w1s;
            float bb[4], cc[4];
#pragma unroll
            for (int q = 0; q < 4; q++) { bb[q] = sbc[4 * h1 + q]; cc[q] = sbc[16 + 4 * w1 + q]; }
            float bcp[16];
#pragma unroll
            for (int i0 = 0; i0 < 4; i0++)
#pragma unroll
                for (int j0 = 0; j0 < 4; j0++)
                    bcp[i0 * 4 + j0] = bb[i0] * cc[j0];

            float u0[4], u1[4];
#pragma unroll
            for (int hh = 0; hh < 2; hh++)
#pragma unroll
                for (int ww = 0; ww < 2; ww++) {
                    const int q = hh * 2 + ww;
                    float v0, v1;
                    v0 =      w0r[0] * bcp[(2 * hh) * 4 + 2 * ww];
                    v0 = fmaf(w0r[1],  bcp[(2 * hh) * 4 + 2 * ww + 1], v0);
                    v0 = fmaf(w0r[2],  bcp[(2 * hh + 1) * 4 + 2 * ww], v0);
                    v0 = fmaf(w0r[3],  bcp[(2 * hh + 1) * 4 + 2 * ww + 1], v0);
                    v1 =      w0r[4] * bcp[(2 * hh) * 4 + 2 * ww];
                    v1 = fmaf(w0r[5],  bcp[(2 * hh) * 4 + 2 * ww + 1], v1);
                    v1 = fmaf(w0r[6],  bcp[(2 * hh + 1) * 4 + 2 * ww], v1);
                    v1 = fmaf(w0r[7],  bcp[(2 * hh + 1) * 4 + 2 * ww + 1], v1);
                    u0[q] = v0; u1[q] = v1;
                }

#pragma unroll
            for (int d1 = 0; d1 < 4; d1++) {
                const float a0 = ar[4 * d1 + 0], a1 = ar[4 * d1 + 1];
                const float a2 = ar[4 * d1 + 2], a3 = ar[4 * d1 + 3];
                float y[8];
#pragma unroll
                for (int q = 0; q < 4; q++) {
                    y[q]     = fmaxf(fmaf(u1[q], a1, fmaf(u0[q], a0, bias0)), 0.f);
                    y[4 + q] = fmaxf(fmaf(u1[q], a3, fmaf(u0[q], a2, bias0)), 0.f);
                }
                const int r = w1s * 4 + d1;
                ((float4*)act1)[r * 64 + g]      = make_float4(y[0], y[1], y[2], y[3]); // dd=0
                ((float4*)act1)[r * 64 + 32 + g] = make_float4(y[4], y[5], y[6], y[7]); // dd=1
            }
        }
        __syncwarp();

        // --- conv1: 8 outputs per lane in one pass over W1 (packed f32x2) ---
        unsigned long long acc[8];
#pragma unroll
        for (int r = 0; r < 8; r++) acc[r] = 0ull;
#pragma unroll 4
        for (int kb = 0; kb < 64; kb++) {
            const ulonglong2 w = wv1[kb * 32];
#pragma unroll
            for (int r = 0; r < 8; r++) {
                const ulonglong2 x = act1u[r * 64 + kb];
                ffma2(acc[r], w.x, x.x);
                ffma2(acc[r], w.y, x.y);
            }
        }

        // --- relu + scatter into conv2 im2col ---
        const int h2 = h1 >> 1, hh2 = h1 & 1;
#pragma unroll
        for (int r = 0; r < 8; r++) {
            const int w1s = r >> 2, d1 = r & 3;
            const int d2 = d1 >> 1, dd2 = d1 & 1;
            const float2 p = upk2(acc[r]);
            const float s = fmaxf(p.x + p.y + bias1, 0.f);
            const int p2 = d2 * 4 + h2 * 2 + w1p;          // w2 == w1p
            act2[p2 * 256 + dd2 * 128 + g * 4 + hh2 * 2 + w1s] = s;
        }
        __syncwarp();
    }

    // ---- repack Wp1 <- W3 (conv1 done block-wide) ----
    __syncthreads();
    {
        const float4* w3v = (const float4*)W3;
        float4* p1 = (float4*)Wp1;
        for (int e = tid; e < 2048; e += THREADS) {
            int gg = e >> 6, rem = e & 63, cc_ = rem >> 1, hf = rem & 1;
            p1[(hf * 32 + cc_) * 32 + gg] = w3v[e];
        }
    }
    __syncthreads();

    // ================= conv2: all 8 positions in one weight pass =================
    {
        unsigned long long q[8];
#pragma unroll
        for (int p2 = 0; p2 < 8; p2++) q[p2] = 0ull;
#pragma unroll 2
        for (int kb = 0; kb < 64; kb++) {
            const ulonglong2 w = wv2[kb * 32];
#pragma unroll
            for (int p2 = 0; p2 < 8; p2++) {
                const ulonglong2 x = act2u[p2 * 64 + kb];
                ffma2(q[p2], w.x, x.x);
                ffma2(q[p2], w.y, x.y);
            }
        }
        float y2[8];
#pragma unroll
        for (int p2 = 0; p2 < 8; p2++) {
            const float2 p = upk2(q[p2]);
            y2[p2] = fmaxf(p.x + p.y + bias2, 0.f);
        }
        ((float4*)act3)[g]      = make_float4(y2[0], y2[1], y2[2], y2[3]); // half=0
        ((float4*)act3)[32 + g] = make_float4(y2[4], y2[5], y2[6], y2[7]); // half=1
    }
    __syncwarp();

    // ================= conv3 + fc + sigmoid =================
    {
        const ulonglong2* wv3 = ((const ulonglong2*)Wp1) + g;
        unsigned long long e0 = 0ull, e1 = 0ull;
#pragma unroll 8
        for (int kb = 0; kb < 64; kb++) {
            const ulonglong2 w = wv3[kb * 32];
            const ulonglong2 x = act3u[kb];
            ffma2(e0, w.x, x.x);
            ffma2(e1, w.y, x.y);
        }
        const float2 pa = upk2(e0), pb = upk2(e1);
        const float y3 = fmaxf((pa.x + pa.y) + (pb.x + pb.y) + bias3, 0.f);
        float v = y3 * fcwg;
#pragma unroll
        for (int off = 16; off > 0; off >>= 1)
            v += __shfl_xor_sync(0xffffffffu, v, off);
        if (lane == 0) {
            const float z = v + fcb[0];
            out[sample] = 1.0f / (1.0f + expf(-z));
        }
    }
}

extern "C" void kernel_launch(void* const* d_in, const int* in_sizes, int n_in,
                              void* d_out, int out_size)
{
    const int*   gi  = (const int*)  d_in[0];
    const int*   gj  = (const int*)  d_in[1];
    const int*   gk  = (const int*)  d_in[2];
    const float* A   = (const float*)d_in[3];
    const float* Bm  = (const float*)d_in[4];
    const float* Cm  = (const float*)d_in[5];
    const float* W0  = (const float*)d_in[6];
    const float* b0  = (const float*)d_in[7];
    const float* W1  = (const float*)d_in[8];
    const float* b1  = (const float*)d_in[9];
    const float* W2  = (const float*)d_in[10];
    const float* b2  = (const float*)d_in[11];
    const float* W3  = (const float*)d_in[12];
    const float* b3  = (const float*)d_in[13];
    const float* fcw = (const float*)d_in[14];
    const float* fcb = (const float*)d_in[15];
    float* out = (float*)d_out;

    const int batch  = in_sizes[0];
    const int blocks = batch / WPB;
    const size_t smemBytes = (size_t)(2 * WPFL + WPB * SSTR) * sizeof(float);

    cudaFuncSetAttribute(NTC_30202210025785_kernel,
                         cudaFuncAttributeMaxDynamicSharedMemorySize, (int)smemBytes);

    NTC_30202210025785_kernel<<<blocks, THREADS, smemBytes>>>(
        gi, gj, gk, A, Bm, Cm, W0, b0, W1, b1, W2, b2, W3, b3, fcw, fcb, out);
}